// round 8
// baseline (speedup 1.0000x reference)
#include <cuda_runtime.h>

// AccuracyMetricLoss: per-day (96-elem) RMS relative-error score, mean over days.
// score_d = (1 - sqrt(mean_j ((t-p)/max(t,thresh))^2)) * 100 ; out = mean_d score_d
//
// R8: R5 config (best measured: ncu 30.08us, ~100% of the empirical 5.1TB/s
// streaming ceiling) with two probes:
//  - default cached loads instead of __ldcs (the ONE dimension never varied;
//    tests whether evict-first policy induces the 5.1TB/s cap),
//  - leaner last-block finalize (shorter serialized tail).
// Layout: 8-lanes-per-day float4, 6 batched LDG.128/trip, contiguous per-warp
// day ranges, __launch_bounds__(256,4), 592 blocks.

#define T_LEN 96
#define F4_PER_DAY 24
#define NBLOCKS 592          // 4 * 148 SMs
#define NTHREADS 256
#define WARPS_PER_BLOCK (NTHREADS / 32)
#define TOTAL_WARPS (NBLOCKS * WARPS_PER_BLOCK)

__device__ float g_partials[NBLOCKS];
__device__ unsigned int g_counter = 0;

__device__ __forceinline__ float day_err_sq(float4 t, float4 p, float thresh)
{
    float d0 = (t.x > thresh) ? t.x : thresh;
    float d1 = (t.y > thresh) ? t.y : thresh;
    float d2 = (t.z > thresh) ? t.z : thresh;
    float d3 = (t.w > thresh) ? t.w : thresh;
    float e0 = __fdividef(t.x - p.x, d0);
    float e1 = __fdividef(t.y - p.y, d1);
    float e2 = __fdividef(t.z - p.z, d2);
    float e3 = __fdividef(t.w - p.w, d3);
    return e0 * e0 + e1 * e1 + e2 * e2 + e3 * e3;
}

__global__ __launch_bounds__(NTHREADS, 4) void score_kernel(
    const float* __restrict__ pred,
    const float* __restrict__ tru,
    float* __restrict__ out,
    int num_days)
{
    const float cap    = 1602.1333333333334f;
    const float thresh = 0.2f * cap;
    const float inv_T  = 1.0f / 96.0f;

    const int lane = threadIdx.x & 31;
    const int g    = lane >> 3;          // day group within warp (0..3)
    const int k    = lane & 7;           // lane within group
    const int warp = (blockIdx.x * WARPS_PER_BLOCK) + (threadIdx.x >> 5);

    const float4* __restrict__ tru4  = (const float4*)tru;
    const float4* __restrict__ pred4 = (const float4*)pred;

    // contiguous per-warp day range: near-perfect balance (<=1 day skew)
    int day_s = (int)(((long)warp       * num_days) / TOTAL_WARPS);
    int day_e = (int)(((long)(warp + 1) * num_days) / TOTAL_WARPS);

    float acc = 0.0f;

    int day = day_s;
    for (; day + 4 <= day_e; day += 4) {
        // 6 fully-coalesced LDG.128 per warp, batched; default cache policy
        const long b = (long)(day + g) * F4_PER_DAY + k;
        float4 t0 = tru4 [b];
        float4 t1 = tru4 [b + 8];
        float4 t2 = tru4 [b + 16];
        float4 p0 = pred4[b];
        float4 p1 = pred4[b + 8];
        float4 p2 = pred4[b + 16];

        float r = day_err_sq(t0, p0, thresh)
                + day_err_sq(t1, p1, thresh)
                + day_err_sq(t2, p2, thresh);

        // reduce within 8-lane group (xor of low 3 bits stays in-group)
        r += __shfl_xor_sync(0xffffffffu, r, 4);
        r += __shfl_xor_sync(0xffffffffu, r, 2);
        r += __shfl_xor_sync(0xffffffffu, r, 1);

        acc += (1.0f - sqrtf(r * inv_T)) * 100.0f;   // counted 8x per day
    }

    // tail: 0..3 days, groups g < nd active, same float4 path
    {
        const int nd = day_e - day;
        if (nd > 0) {
            float r = 0.0f;
            if (g < nd) {
                const long b = (long)(day + g) * F4_PER_DAY + k;
                float4 t0 = tru4 [b];
                float4 t1 = tru4 [b + 8];
                float4 t2 = tru4 [b + 16];
                float4 p0 = pred4[b];
                float4 p1 = pred4[b + 8];
                float4 p2 = pred4[b + 16];
                r = day_err_sq(t0, p0, thresh)
                  + day_err_sq(t1, p1, thresh)
                  + day_err_sq(t2, p2, thresh);
            }
            r += __shfl_xor_sync(0xffffffffu, r, 4);
            r += __shfl_xor_sync(0xffffffffu, r, 2);
            r += __shfl_xor_sync(0xffffffffu, r, 1);
            if (g < nd)
                acc += (1.0f - sqrtf(r * inv_T)) * 100.0f;
        }
    }

    // warp sum, then block reduce into g_partials[blockIdx.x]
    #pragma unroll
    for (int o = 16; o > 0; o >>= 1)
        acc += __shfl_xor_sync(0xffffffffu, acc, o);

    __shared__ float warp_acc[WARPS_PER_BLOCK];
    if (lane == 0) warp_acc[threadIdx.x >> 5] = acc;
    __syncthreads();

    __shared__ bool is_last;
    if (threadIdx.x == 0) {
        float v = 0.0f;
        #pragma unroll
        for (int w = 0; w < WARPS_PER_BLOCK; w++) v += warp_acc[w];
        g_partials[blockIdx.x] = v;
        __threadfence();
        unsigned int prev = atomicAdd(&g_counter, 1u);
        is_last = (prev == (unsigned int)(gridDim.x - 1));
    }
    __syncthreads();

    // last block finalizes. Single warp: 592 partials -> fixed-order double sum.
    // (one warp avoids the extra smem round + syncthreads of a 256-thread pass;
    // 19 L2-hit loads/lane pipeline, then one 5-step shuffle tree)
    if (is_last && threadIdx.x < 32) {
        double a = 0.0;
        for (int i = threadIdx.x; i < NBLOCKS; i += 32)
            a += (double)__ldg(&g_partials[i]);
        #pragma unroll
        for (int o = 16; o > 0; o >>= 1)
            a += __shfl_xor_sync(0xffffffffu, a, o);
        if (threadIdx.x == 0) {
            out[0] = (float)(a / (8.0 * (double)num_days));
            g_counter = 0;           // reset for next graph replay
            __threadfence();
        }
    }
}

extern "C" void kernel_launch(void* const* d_in, const int* in_sizes, int n_in,
                              void* d_out, int out_size)
{
    const float* pred = (const float*)d_in[0];
    const float* tru  = (const float*)d_in[1];
    float* out = (float*)d_out;

    int num_days = in_sizes[0] / T_LEN;

    score_kernel<<<NBLOCKS, NTHREADS>>>(pred, tru, out, num_days);
}

// round 9
// speedup vs baseline: 1.0009x; 1.0009x over previous
#include <cuda_runtime.h>

// AccuracyMetricLoss: per-day (96-elem) RMS relative-error score, mean over days.
// score_d = (1 - sqrt(mean_j ((t-p)/max(t,thresh))^2)) * 100 ; out = mean_d score_d
//
// R9 (final form): R5 config — the best measured operating point (kernel
// 30.08us, ~5.2TB/s, which the R4-R8 experiment matrix showed is the
// empirical streaming ceiling here) — plus R8's leaner single-warp finalize.
//  - 8-lanes-per-day float4 layout: 6 batched, fully-coalesced LDG.128/trip.
//  - __ldcs (evict-first) is REQUIRED: default policy thrashes L2 (R8: +6us).
//  - __launch_bounds__(256,4), 592 blocks, contiguous per-warp day ranges.
//  - last-block-finalizes: single-warp fixed-order double sum, counter reset.

#define T_LEN 96
#define F4_PER_DAY 24
#define NBLOCKS 592          // 4 * 148 SMs
#define NTHREADS 256
#define WARPS_PER_BLOCK (NTHREADS / 32)
#define TOTAL_WARPS (NBLOCKS * WARPS_PER_BLOCK)

__device__ float g_partials[NBLOCKS];
__device__ unsigned int g_counter = 0;

__device__ __forceinline__ float day_err_sq(float4 t, float4 p, float thresh)
{
    float d0 = (t.x > thresh) ? t.x : thresh;
    float d1 = (t.y > thresh) ? t.y : thresh;
    float d2 = (t.z > thresh) ? t.z : thresh;
    float d3 = (t.w > thresh) ? t.w : thresh;
    float e0 = __fdividef(t.x - p.x, d0);
    float e1 = __fdividef(t.y - p.y, d1);
    float e2 = __fdividef(t.z - p.z, d2);
    float e3 = __fdividef(t.w - p.w, d3);
    return e0 * e0 + e1 * e1 + e2 * e2 + e3 * e3;
}

__global__ __launch_bounds__(NTHREADS, 4) void score_kernel(
    const float* __restrict__ pred,
    const float* __restrict__ tru,
    float* __restrict__ out,
    int num_days)
{
    const float cap    = 1602.1333333333334f;
    const float thresh = 0.2f * cap;
    const float inv_T  = 1.0f / 96.0f;

    const int lane = threadIdx.x & 31;
    const int g    = lane >> 3;          // day group within warp (0..3)
    const int k    = lane & 7;           // lane within group
    const int warp = (blockIdx.x * WARPS_PER_BLOCK) + (threadIdx.x >> 5);

    const float4* __restrict__ tru4  = (const float4*)tru;
    const float4* __restrict__ pred4 = (const float4*)pred;

    // contiguous per-warp day range: near-perfect balance (<=1 day skew)
    int day_s = (int)(((long)warp       * num_days) / TOTAL_WARPS);
    int day_e = (int)(((long)(warp + 1) * num_days) / TOTAL_WARPS);

    float acc = 0.0f;

    int day = day_s;
    for (; day + 4 <= day_e; day += 4) {
        // 6 fully-coalesced LDG.128 per warp, batched, evict-first
        const long b = (long)(day + g) * F4_PER_DAY + k;
        float4 t0 = __ldcs(tru4  + b);
        float4 t1 = __ldcs(tru4  + b + 8);
        float4 t2 = __ldcs(tru4  + b + 16);
        float4 p0 = __ldcs(pred4 + b);
        float4 p1 = __ldcs(pred4 + b + 8);
        float4 p2 = __ldcs(pred4 + b + 16);

        float r = day_err_sq(t0, p0, thresh)
                + day_err_sq(t1, p1, thresh)
                + day_err_sq(t2, p2, thresh);

        // reduce within 8-lane group (xor of low 3 bits stays in-group)
        r += __shfl_xor_sync(0xffffffffu, r, 4);
        r += __shfl_xor_sync(0xffffffffu, r, 2);
        r += __shfl_xor_sync(0xffffffffu, r, 1);

        acc += (1.0f - sqrtf(r * inv_T)) * 100.0f;   // counted 8x per day
    }

    // tail: 0..3 days, groups g < nd active, same float4 path
    {
        const int nd = day_e - day;
        if (nd > 0) {
            float r = 0.0f;
            if (g < nd) {
                const long b = (long)(day + g) * F4_PER_DAY + k;
                float4 t0 = __ldcs(tru4  + b);
                float4 t1 = __ldcs(tru4  + b + 8);
                float4 t2 = __ldcs(tru4  + b + 16);
                float4 p0 = __ldcs(pred4 + b);
                float4 p1 = __ldcs(pred4 + b + 8);
                float4 p2 = __ldcs(pred4 + b + 16);
                r = day_err_sq(t0, p0, thresh)
                  + day_err_sq(t1, p1, thresh)
                  + day_err_sq(t2, p2, thresh);
            }
            r += __shfl_xor_sync(0xffffffffu, r, 4);
            r += __shfl_xor_sync(0xffffffffu, r, 2);
            r += __shfl_xor_sync(0xffffffffu, r, 1);
            if (g < nd)
                acc += (1.0f - sqrtf(r * inv_T)) * 100.0f;
        }
    }

    // warp sum, then block reduce into g_partials[blockIdx.x]
    #pragma unroll
    for (int o = 16; o > 0; o >>= 1)
        acc += __shfl_xor_sync(0xffffffffu, acc, o);

    __shared__ float warp_acc[WARPS_PER_BLOCK];
    if (lane == 0) warp_acc[threadIdx.x >> 5] = acc;
    __syncthreads();

    __shared__ bool is_last;
    if (threadIdx.x == 0) {
        float v = 0.0f;
        #pragma unroll
        for (int w = 0; w < WARPS_PER_BLOCK; w++) v += warp_acc[w];
        g_partials[blockIdx.x] = v;
        __threadfence();
        unsigned int prev = atomicAdd(&g_counter, 1u);
        is_last = (prev == (unsigned int)(gridDim.x - 1));
    }
    __syncthreads();

    // last block finalizes. Single warp: 592 partials -> fixed-order double sum
    // (no extra smem round / syncthreads on the serialized tail).
    if (is_last && threadIdx.x < 32) {
        double a = 0.0;
        for (int i = threadIdx.x; i < NBLOCKS; i += 32)
            a += (double)__ldg(&g_partials[i]);
        #pragma unroll
        for (int o = 16; o > 0; o >>= 1)
            a += __shfl_xor_sync(0xffffffffu, a, o);
        if (threadIdx.x == 0) {
            out[0] = (float)(a / (8.0 * (double)num_days));
            g_counter = 0;           // reset for next graph replay
            __threadfence();
        }
    }
}

extern "C" void kernel_launch(void* const* d_in, const int* in_sizes, int n_in,
                              void* d_out, int out_size)
{
    const float* pred = (const float*)d_in[0];
    const float* tru  = (const float*)d_in[1];
    float* out = (float*)d_out;

    int num_days = in_sizes[0] / T_LEN;

    score_kernel<<<NBLOCKS, NTHREADS>>>(pred, tru, out, num_days);
}

// round 10
// speedup vs baseline: 1.2059x; 1.2049x over previous
#include <cuda_runtime.h>

// AccuracyMetricLoss: per-day (96-elem) RMS relative-error score, mean over days.
// score_d = (1 - sqrt(mean_j ((t-p)/max(t,thresh))^2)) * 100 ; out = mean_d score_d
//
// R10: exact resubmission of R5 — the best measured configuration (31.2us
// bench / 30.08us ncu, ~5.2TB/s). R8/R9 (37.6-37.7us) shared NO unique code
// with each other's regressions once __ldcs was restored; their uniform
// all-pipe slowdown vs identical main-loop SASS points to NAT clock drift.
// This run discriminates: ~31us => R5 reconfirmed; ~37us => environment.
//
//  - 8-lanes-per-day float4 layout (6 batched, fully-coalesced LDG.128/trip).
//  - __ldcs evict-first streaming loads (dataset 153.6MB >> 126MB L2).
//  - __launch_bounds__(256,4), 592 blocks, contiguous per-warp day ranges.
//  - last-block-finalizes (deterministic fixed-order double sum, counter reset).

#define T_LEN 96
#define F4_PER_DAY 24
#define NBLOCKS 592          // 4 * 148 SMs
#define NTHREADS 256         // 8 warps/block
#define WARPS_PER_BLOCK (NTHREADS / 32)
#define TOTAL_WARPS (NBLOCKS * WARPS_PER_BLOCK)

__device__ float g_partials[NBLOCKS];
__device__ unsigned int g_counter = 0;

__device__ __forceinline__ float day_err_sq(float4 t, float4 p, float thresh)
{
    float d0 = (t.x > thresh) ? t.x : thresh;
    float d1 = (t.y > thresh) ? t.y : thresh;
    float d2 = (t.z > thresh) ? t.z : thresh;
    float d3 = (t.w > thresh) ? t.w : thresh;
    float e0 = __fdividef(t.x - p.x, d0);
    float e1 = __fdividef(t.y - p.y, d1);
    float e2 = __fdividef(t.z - p.z, d2);
    float e3 = __fdividef(t.w - p.w, d3);
    return e0 * e0 + e1 * e1 + e2 * e2 + e3 * e3;
}

__global__ __launch_bounds__(NTHREADS, 4) void score_kernel(
    const float* __restrict__ pred,
    const float* __restrict__ tru,
    float* __restrict__ out,
    int num_days)
{
    const float cap    = 1602.1333333333334f;
    const float thresh = 0.2f * cap;
    const float inv_T  = 1.0f / 96.0f;

    const int lane = threadIdx.x & 31;
    const int g    = lane >> 3;          // day group within warp (0..3)
    const int k    = lane & 7;           // lane within group
    const int warp = (blockIdx.x * WARPS_PER_BLOCK) + (threadIdx.x >> 5);

    const float4* __restrict__ tru4  = (const float4*)tru;
    const float4* __restrict__ pred4 = (const float4*)pred;

    // contiguous per-warp day range: near-perfect balance (<=1 day skew)
    int day_s = (int)(((long)warp       * num_days) / TOTAL_WARPS);
    int day_e = (int)(((long)(warp + 1) * num_days) / TOTAL_WARPS);

    float acc = 0.0f;

    int day = day_s;
    for (; day + 4 <= day_e; day += 4) {
        // 6 fully-coalesced LDG.128 per warp, batched
        const long b = (long)(day + g) * F4_PER_DAY + k;
        float4 t0 = __ldcs(tru4  + b);
        float4 t1 = __ldcs(tru4  + b + 8);
        float4 t2 = __ldcs(tru4  + b + 16);
        float4 p0 = __ldcs(pred4 + b);
        float4 p1 = __ldcs(pred4 + b + 8);
        float4 p2 = __ldcs(pred4 + b + 16);

        float r = day_err_sq(t0, p0, thresh)
                + day_err_sq(t1, p1, thresh)
                + day_err_sq(t2, p2, thresh);

        // reduce within 8-lane group (xor of low 3 bits stays in-group)
        r += __shfl_xor_sync(0xffffffffu, r, 4);
        r += __shfl_xor_sync(0xffffffffu, r, 2);
        r += __shfl_xor_sync(0xffffffffu, r, 1);

        acc += (1.0f - sqrtf(r * inv_T)) * 100.0f;   // counted 8x per day
    }

    // tail: 0..3 days, groups g < nd active, same float4 path
    {
        const int nd = day_e - day;
        if (nd > 0) {
            float r = 0.0f;
            if (g < nd) {
                const long b = (long)(day + g) * F4_PER_DAY + k;
                float4 t0 = __ldcs(tru4  + b);
                float4 t1 = __ldcs(tru4  + b + 8);
                float4 t2 = __ldcs(tru4  + b + 16);
                float4 p0 = __ldcs(pred4 + b);
                float4 p1 = __ldcs(pred4 + b + 8);
                float4 p2 = __ldcs(pred4 + b + 16);
                r = day_err_sq(t0, p0, thresh)
                  + day_err_sq(t1, p1, thresh)
                  + day_err_sq(t2, p2, thresh);
            }
            r += __shfl_xor_sync(0xffffffffu, r, 4);
            r += __shfl_xor_sync(0xffffffffu, r, 2);
            r += __shfl_xor_sync(0xffffffffu, r, 1);
            if (g < nd)
                acc += (1.0f - sqrtf(r * inv_T)) * 100.0f;
        }
    }

    // warp sum, then block reduce into g_partials[blockIdx.x]
    #pragma unroll
    for (int o = 16; o > 0; o >>= 1)
        acc += __shfl_xor_sync(0xffffffffu, acc, o);

    __shared__ float warp_acc[WARPS_PER_BLOCK];
    if (lane == 0) warp_acc[threadIdx.x >> 5] = acc;
    __syncthreads();

    __shared__ bool is_last;
    if (threadIdx.x == 0) {
        float v = 0.0f;
        #pragma unroll
        for (int w = 0; w < WARPS_PER_BLOCK; w++) v += warp_acc[w];
        g_partials[blockIdx.x] = v;
        __threadfence();
        unsigned int prev = atomicAdd(&g_counter, 1u);
        is_last = (prev == (unsigned int)(gridDim.x - 1));
    }
    __syncthreads();

    // last block finalizes: fixed-order double reduction over NBLOCKS partials
    if (is_last) {
        double a = 0.0;
        for (int i = threadIdx.x; i < NBLOCKS; i += NTHREADS)
            a += (double)g_partials[i];

        __shared__ double dacc[WARPS_PER_BLOCK];
        #pragma unroll
        for (int o = 16; o > 0; o >>= 1)
            a += __shfl_xor_sync(0xffffffffu, a, o);
        if (lane == 0) dacc[threadIdx.x >> 5] = a;
        __syncthreads();
        if (threadIdx.x == 0) {
            double s = 0.0;
            #pragma unroll
            for (int w = 0; w < WARPS_PER_BLOCK; w++) s += dacc[w];
            out[0] = (float)(s / (8.0 * (double)num_days));
            g_counter = 0;           // reset for next graph replay
            __threadfence();
        }
    }
}

extern "C" void kernel_launch(void* const* d_in, const int* in_sizes, int n_in,
                              void* d_out, int out_size)
{
    const float* pred = (const float*)d_in[0];
    const float* tru  = (const float*)d_in[1];
    float* out = (float*)d_out;

    int num_days = in_sizes[0] / T_LEN;

    score_kernel<<<NBLOCKS, NTHREADS>>>(pred, tru, out, num_days);
}